// round 11
// baseline (speedup 1.0000x reference)
#include <cuda_runtime.h>
#include <cuda_fp16.h>
#include <stdint.h>

// ---------------- problem constants ----------------
constexpr int B = 2, H = 16, S = 2048, D = 64;
constexpr int BH = B * H;
constexpr float INV_T = 1.0f / 32.0f;

constexpr int QT = 128;           // query rows per CTA
constexpr int NT = 128;           // keys per tile
constexpr int NTILES = S / NT;    // 16
constexpr int THREADS = 256;      // 8 warps, warp w owns q-rows 16w..16w+15

// XOR-swizzled tile: 128 rows x 128B; chunk c of row r at r*128 + ((c^(r&7))*16)
constexpr int TILE_B = 128 * 128;               // 16384
constexpr int SM_K0   = 0;
constexpr int SM_K1   = TILE_B;
constexpr int SM_V0   = 2 * TILE_B;
constexpr int SM_V1   = 3 * TILE_B;
constexpr int SM_MASK = 4 * TILE_B;             // 2048 floats
constexpr int SMEM_SZ = SM_MASK + S * 4;        // 73728 B -> 3 CTAs/SM

// ---------------- device fp16 copies ----------------
__device__ __half g_q16[(size_t)BH * S * D];
__device__ __half g_k16[(size_t)BH * S * D];
__device__ __half g_v16[(size_t)BH * S * D];

// ---------------- helpers ----------------
__device__ __forceinline__ uint32_t su32(const void* p) {
    uint32_t a;
    asm("{ .reg .u64 t; cvta.to.shared.u64 t, %1; cvt.u32.u64 %0, t; }" : "=r"(a) : "l"(p));
    return a;
}
__device__ __forceinline__ void cpa16(uint32_t d, const void* s) {
    asm volatile("cp.async.cg.shared.global [%0], [%1], 16;" :: "r"(d), "l"(s));
}
#define CP_COMMIT() asm volatile("cp.async.commit_group;" ::: "memory")
#define CP_WAIT0()  asm volatile("cp.async.wait_group 0;" ::: "memory")

#define LDSM4(r0, r1, r2, r3, a) \
    asm volatile("ldmatrix.sync.aligned.m8n8.x4.shared.b16 {%0,%1,%2,%3}, [%4];" \
                 : "=r"(r0), "=r"(r1), "=r"(r2), "=r"(r3) : "r"(a))
#define LDSM4T(r0, r1, r2, r3, a) \
    asm volatile("ldmatrix.sync.aligned.m8n8.x4.trans.shared.b16 {%0,%1,%2,%3}, [%4];" \
                 : "=r"(r0), "=r"(r1), "=r"(r2), "=r"(r3) : "r"(a))

__device__ __forceinline__ void mma_f16(float4& c, const uint32_t a[4],
                                        uint32_t b0, uint32_t b1) {
    asm volatile(
        "mma.sync.aligned.m16n8k16.row.col.f32.f16.f16.f32 "
        "{%0,%1,%2,%3}, {%4,%5,%6,%7}, {%8,%9}, {%0,%1,%2,%3};"
        : "+f"(c.x), "+f"(c.y), "+f"(c.z), "+f"(c.w)
        : "r"(a[0]), "r"(a[1]), "r"(a[2]), "r"(a[3]), "r"(b0), "r"(b1));
}
__device__ __forceinline__ void mma_f16u(float4& c, uint32_t a0, uint32_t a1,
                                         uint32_t a2, uint32_t a3,
                                         uint32_t b0, uint32_t b1) {
    asm volatile(
        "mma.sync.aligned.m16n8k16.row.col.f32.f16.f16.f32 "
        "{%0,%1,%2,%3}, {%4,%5,%6,%7}, {%8,%9}, {%0,%1,%2,%3};"
        : "+f"(c.x), "+f"(c.y), "+f"(c.z), "+f"(c.w)
        : "r"(a0), "r"(a1), "r"(a2), "r"(a3), "r"(b0), "r"(b1));
}
__device__ __forceinline__ uint32_t packh2(float a, float b) {
    __half2 h = __floats2half2_rn(a, b);
    return *(uint32_t*)&h;
}
__device__ __forceinline__ float2 shfl_xor_f2(float2 v, int m) {
    v.x = __shfl_xor_sync(0xffffffffu, v.x, m);
    v.y = __shfl_xor_sync(0xffffffffu, v.y, m);
    return v;
}
// 4x4 transpose of float2 a[4] across a quad of lanes (q = lane&3).
__device__ __forceinline__ void quad_transpose_f2(float2 a[4], int q) {
    {
        float2 v = (q & 1) ? a[0] : a[1];
        v = shfl_xor_f2(v, 1);
        if (q & 1) a[0] = v; else a[1] = v;
        float2 u = (q & 1) ? a[2] : a[3];
        u = shfl_xor_f2(u, 1);
        if (q & 1) a[2] = u; else a[3] = u;
    }
    {
        float2 v = (q & 2) ? a[0] : a[2];
        v = shfl_xor_f2(v, 2);
        if (q & 2) a[0] = v; else a[2] = v;
        float2 u = (q & 2) ? a[1] : a[3];
        u = shfl_xor_f2(u, 2);
        if (q & 2) a[1] = u; else a[3] = u;
    }
}

// 128-row fp16 tile -> swizzled smem (256 threads, 4 chunks each)
__device__ __forceinline__ void load_tile(uint32_t sdst, const __half* g, int tid) {
#pragma unroll
    for (int it = 0; it < 4; it++) {
        int f = tid + it * THREADS;
        int r = f >> 3, c = f & 7;
        cpa16(sdst + r * 128 + ((c ^ (r & 7)) << 4), g + r * 64 + c * 8);
    }
}

// ---------------- prep: fp32 -> fp16 (Q scaled by 1/T) ----------------
__global__ void prep16(const float* __restrict__ q, const float* __restrict__ k,
                       const float* __restrict__ v) {
    const int N4 = BH * S * D / 4;
    int i = blockIdx.x * blockDim.x + threadIdx.x;
    if (i >= N4) return;
    float4 a = ((const float4*)q)[i];
    float4 b = ((const float4*)k)[i];
    float4 c = ((const float4*)v)[i];
    __half2* q2 = (__half2*)g_q16;
    __half2* k2 = (__half2*)g_k16;
    __half2* v2 = (__half2*)g_v16;
    q2[2 * i]     = __floats2half2_rn(a.x * INV_T, a.y * INV_T);
    q2[2 * i + 1] = __floats2half2_rn(a.z * INV_T, a.w * INV_T);
    k2[2 * i]     = __floats2half2_rn(b.x, b.y);
    k2[2 * i + 1] = __floats2half2_rn(b.z, b.w);
    v2[2 * i]     = __floats2half2_rn(c.x, c.y);
    v2[2 * i + 1] = __floats2half2_rn(c.z, c.w);
}

// ---------------- main fused attention ----------------
__global__ __launch_bounds__(THREADS, 3)
void attn_main(const int* __restrict__ mask,
               float* __restrict__ out, float* __restrict__ attn)
{
    extern __shared__ char smem[];
    const uint32_t sb = su32(smem);
    const int tid = threadIdx.x;
    const int w   = tid >> 5;
    const int L   = tid & 31;
    const int q_  = L & 3;
    const int lrow = L & 7;
    const int lsel = L >> 3;
    const int bh  = blockIdx.y;
    const int q0  = blockIdx.x * QT;

    const __half* qg = g_q16 + ((size_t)bh * S + q0) * D;
    const __half* kg = g_k16 + (size_t)bh * S * D;
    const __half* vg = g_v16 + (size_t)bh * S * D;

    const uint32_t sK[2] = { sb + SM_K0, sb + SM_K1 };
    const uint32_t sV[2] = { sb + SM_V0, sb + SM_V1 };
    float* mf = (float*)(smem + SM_MASK);

    load_tile(sK[0], kg, tid);
    load_tile(sV[0], vg, tid);
    CP_COMMIT();
    {
        const int* mp = mask + (size_t)(bh >> 4) * S;
        for (int i = tid; i < S; i += THREADS) mf[i] = mp[i] ? 1.0f : 0.0f;
    }

    // Q fragments straight from global (m16n8k16 A layout)
    uint32_t qa[4][4];
    {
        const __half* qr0 = qg + (w * 16 + (L >> 2)) * 64 + 2 * (L & 3);
        const __half* qr1 = qr0 + 8 * 64;
#pragma unroll
        for (int ks = 0; ks < 4; ks++) {
            qa[ks][0] = *(const uint32_t*)(qr0 + 16 * ks);
            qa[ks][1] = *(const uint32_t*)(qr1 + 16 * ks);
            qa[ks][2] = *(const uint32_t*)(qr0 + 16 * ks + 8);
            qa[ks][3] = *(const uint32_t*)(qr1 + 16 * ks + 8);
        }
    }

    CP_WAIT0();
    __syncthreads();

    const uint32_t ksw1 = ((lsel ^ lrow) << 4);            // chunk 0..3 region
    const uint32_t ksw2 = (((lsel + 4) ^ lrow) << 4);      // chunk 4..7 region
    const int      c_base = 2 * q_;

    float inv_lo, inv_hi;

    // ===== pass 1: QK + exp + sums + PV =====
    {
        float4 oc[8];
#pragma unroll
        for (int nb = 0; nb < 8; nb++) oc[nb] = make_float4(0.f, 0.f, 0.f, 0.f);
        float sum_lo = 0.0f, sum_hi = 0.0f;

        for (int kt = 0; kt < NTILES; kt++) {
            const int cur = kt & 1;
            if (kt + 1 < NTILES) {
                load_tile(sK[cur ^ 1], kg + (size_t)(kt + 1) * NT * D, tid);
                load_tile(sV[cur ^ 1], vg + (size_t)(kt + 1) * NT * D, tid);
                CP_COMMIT();
            }
            const float* mrow = mf + kt * NT;

#pragma unroll
            for (int kb2 = 0; kb2 < 4; kb2++) {
                uint32_t a16[2][4];
#pragma unroll
                for (int i = 0; i < 4; i++) {
                    int nb = kb2 * 4 + i;
                    uint32_t kbase = sK[cur] + nb * 1024 + lrow * 128;
                    uint32_t b0, b1, b2, b3, b4, b5, b6, b7;
                    LDSM4(b0, b1, b2, b3, kbase + ksw1);
                    LDSM4(b4, b5, b6, b7, kbase + ksw2);
                    float4 cf = make_float4(0.f, 0.f, 0.f, 0.f);
                    mma_f16(cf, qa[0], b0, b1);
                    mma_f16(cf, qa[1], b2, b3);
                    mma_f16(cf, qa[2], b4, b5);
                    mma_f16(cf, qa[3], b6, b7);
                    int c0 = nb * 8 + c_base;
                    float m0 = mrow[c0], m1 = mrow[c0 + 1];
                    float e0 = __expf(cf.x) * m0;
                    float e1 = __expf(cf.y) * m1;
                    float e2 = __expf(cf.z) * m0;
                    float e3 = __expf(cf.w) * m1;
                    sum_lo += e0 + e1;
                    sum_hi += e2 + e3;
                    a16[i >> 1][(i & 1) * 2]     = packh2(e0, e1);
                    a16[i >> 1][(i & 1) * 2 + 1] = packh2(e2, e3);
                }
#pragma unroll
                for (int nbo = 0; nbo < 8; nbo++) {
                    uint32_t vaddr = sV[cur] + kb2 * 4096 + L * 128 + ((nbo ^ lrow) << 4);
                    uint32_t v0, v1, v2, v3;
                    LDSM4T(v0, v1, v2, v3, vaddr);
                    mma_f16(oc[nbo], a16[0], v0, v1);
                    mma_f16(oc[nbo], a16[1], v2, v3);
                }
            }

            if (kt + 1 < NTILES) CP_WAIT0();
            __syncthreads();
        }

#pragma unroll
        for (int m = 1; m < 4; m <<= 1) {
            sum_lo += __shfl_xor_sync(0xffffffffu, sum_lo, m);
            sum_hi += __shfl_xor_sync(0xffffffffu, sum_hi, m);
        }
        inv_lo = 1.0f / sum_lo;
        inv_hi = 1.0f / sum_hi;

        float* olo = out + ((size_t)bh * S + q0 + w * 16 + (L >> 2)) * D + c_base;
        float* ohi = olo + 8 * D;
#pragma unroll
        for (int nb = 0; nb < 8; nb++) {
            *(float2*)(olo + nb * 8) = make_float2(oc[nb].x * inv_lo, oc[nb].y * inv_lo);
            *(float2*)(ohi + nb * 8) = make_float2(oc[nb].z * inv_hi, oc[nb].w * inv_hi);
        }
    }
    __syncthreads();

    // ===== pass 2: attn write only (QK recompute + exp + transpose + stcs) =====
    {
        float* arow_lo = attn + ((size_t)bh * S + q0 + w * 16 + (L >> 2)) * S;
        float* arow_hi = arow_lo + 8 * (size_t)S;

        load_tile(sK[0], kg, tid);
        CP_COMMIT();
        CP_WAIT0();
        __syncthreads();

        for (int kt = 0; kt < NTILES; kt++) {
            const int cur = kt & 1;
            if (kt + 1 < NTILES) {
                load_tile(sK[cur ^ 1], kg + (size_t)(kt + 1) * NT * D, tid);
                CP_COMMIT();
            }
            const float* mrow = mf + kt * NT;

#pragma unroll
            for (int kb2 = 0; kb2 < 4; kb2++) {
                float4 cf[4];
#pragma unroll
                for (int i = 0; i < 4; i++) {
                    int nb = kb2 * 4 + i;
                    uint32_t kbase = sK[cur] + nb * 1024 + lrow * 128;
                    uint32_t b0, b1, b2, b3, b4, b5, b6, b7;
                    LDSM4(b0, b1, b2, b3, kbase + ksw1);
                    LDSM4(b4, b5, b6, b7, kbase + ksw2);
                    cf[i] = make_float4(0.f, 0.f, 0.f, 0.f);
                    mma_f16(cf[i], qa[0], b0, b1);
                    mma_f16(cf[i], qa[1], b2, b3);
                    mma_f16(cf[i], qa[2], b4, b5);
                    mma_f16(cf[i], qa[3], b6, b7);
                }
                float2 flo[4], fhi[4];
#pragma unroll
                for (int i = 0; i < 4; i++) {
                    int c0 = (kb2 * 4 + i) * 8 + c_base;
                    float m0 = mrow[c0], m1 = mrow[c0 + 1];
                    flo[i] = make_float2(__expf(cf[i].x) * m0 * inv_lo,
                                         __expf(cf[i].y) * m1 * inv_lo);
                    fhi[i] = make_float2(__expf(cf[i].z) * m0 * inv_hi,
                                         __expf(cf[i].w) * m1 * inv_hi);
                }
                quad_transpose_f2(flo, q_);
                quad_transpose_f2(fhi, q_);
                int col = kt * NT + kb2 * 32 + 8 * q_;
                __stcs((float4*)(arow_lo + col),
                       make_float4(flo[0].x, flo[0].y, flo[1].x, flo[1].y));
                __stcs((float4*)(arow_lo + col + 4),
                       make_float4(flo[2].x, flo[2].y, flo[3].x, flo[3].y));
                __stcs((float4*)(arow_hi + col),
                       make_float4(fhi[0].x, fhi[0].y, fhi[1].x, fhi[1].y));
                __stcs((float4*)(arow_hi + col + 4),
                       make_float4(fhi[2].x, fhi[2].y, fhi[3].x, fhi[3].y));
            }

            if (kt + 1 < NTILES) CP_WAIT0();
            __syncthreads();
        }
    }
}

// ---------------- launch ----------------
extern "C" void kernel_launch(void* const* d_in, const int* in_sizes, int n_in,
                              void* d_out, int out_size)
{
    const float* q    = (const float*)d_in[0];
    const float* k    = (const float*)d_in[1];
    const float* v    = (const float*)d_in[2];
    const int*   mask = (const int*)  d_in[3];

    float* out  = (float*)d_out;
    float* attn = out + (size_t)BH * S * D;

    cudaFuncSetAttribute(attn_main, cudaFuncAttributeMaxDynamicSharedMemorySize, SMEM_SZ);

    const int N4 = BH * S * D / 4;
    prep16<<<(N4 + 255) / 256, 256>>>(q, k, v);
    attn_main<<<dim3(S / QT, BH), THREADS, SMEM_SZ>>>(mask, out, attn);
}